// round 6
// baseline (speedup 1.0000x reference)
#include <cuda_runtime.h>
#include <cuda_bf16.h>
#include <math.h>

// DynamicVoxelizer: B=8, N=1e6, C=4.
// Output layout (float32, concatenated flattened reference returns):
//   [0)          points_out    B*N*4 = 32,000,000
//   [32000000)   voxel_coords  B*N*3 = 24,000,000  (z,y,x order; -1 if invalid)
//   [56000000)   point_idxes   B*N   =  8,000,000  (n within batch; -1 if invalid)
//   [64000000)   point_offsets B*N*3 = 24,000,000  (xyz - voxel center; 0 if invalid)
//   [88000000)   valid         B*N   =  8,000,000  (1.0 / 0.0)
// total = 96,000,000 floats
//
// NUMERICS: XLA rewrites (x - pmin) / vs into (x - pmin) * rn(1/vs).
// rn(1/0.1f) == 10.0f exactly and rn(1/0.2f) == 5.0f exactly, so the
// reference's cf = floor(diff * {10,10,5}). We reproduce that bit-exactly
// (explicit __fmul_rn/__fadd_rn so nvcc cannot contract or substitute);
// all downstream outputs then match bitwise.

#define BN_TOTAL   8000000
#define N_PER_B    1000000
#define O_COORDS   32000000ull
#define O_IDX      56000000ull
#define O_OFFS     64000000ull
#define O_VALID    88000000ull

__global__ __launch_bounds__(256)
void voxelizer_kernel(const float4* __restrict__ pts, float* __restrict__ out)
{
    int i = blockIdx.x * blockDim.x + threadIdx.x;
    if (i >= BN_TOTAL) return;

    float4 p = pts[i];

    // not_nan over all 4 channels
    bool nn = !(isnan(p.x) || isnan(p.y) || isnan(p.z) || isnan(p.w));

    // cf = floor((xyz - pmin) * rn(1/vs));  rn(1/0.1f)=10.0f, rn(1/0.2f)=5.0f (exact)
    float fx = floorf(__fmul_rn(__fadd_rn(p.x, 51.2f), 10.0f));
    float fy = floorf(__fmul_rn(__fadd_rn(p.y, 51.2f), 10.0f));
    float fz = floorf(__fmul_rn(__fadd_rn(p.z,  5.0f),  5.0f));

    // grid = (1024, 1024, 40); float compares reject NaN naturally
    bool in_range = (fx >= 0.0f) & (fx < 1024.0f)
                  & (fy >= 0.0f) & (fy < 1024.0f)
                  & (fz >= 0.0f) & (fz < 40.0f);

    bool valid = nn && in_range;

    // centers = (cf * vs + pmin) + vs*0.5, exact f32 mul/add, reference op order.
    // vs*0.5 constants: 0.05f == f32(0.1f*0.5f), 0.1f == f32(0.2f*0.5f) (exact).
    float cxc = __fadd_rn(__fadd_rn(__fmul_rn(fx, 0.1f), -51.2f), 0.05f);
    float cyc = __fadd_rn(__fadd_rn(__fmul_rn(fy, 0.1f), -51.2f), 0.05f);
    float czc = __fadd_rn(__fadd_rn(__fmul_rn(fz, 0.2f),  -5.0f), 0.1f);

    // points_out (float4, aligned)
    float4 po = valid ? p : make_float4(0.f, 0.f, 0.f, 0.f);
    reinterpret_cast<float4*>(out)[i] = po;

    // voxel_coords (z, y, x) or -1  (integral-valued floats, exact)
    size_t cbase = O_COORDS + 3ull * (unsigned)i;
    if (valid) {
        out[cbase + 0] = fz;
        out[cbase + 1] = fy;
        out[cbase + 2] = fx;
    } else {
        out[cbase + 0] = -1.0f;
        out[cbase + 1] = -1.0f;
        out[cbase + 2] = -1.0f;
    }

    // point_idxes: n within batch, or -1
    int n = i - (i / N_PER_B) * N_PER_B;
    out[O_IDX + (unsigned)i] = valid ? (float)n : -1.0f;

    // point_offsets: xyz - center (exact f32 sub), or 0
    size_t obase = O_OFFS + 3ull * (unsigned)i;
    if (valid) {
        out[obase + 0] = __fadd_rn(p.x, -cxc);
        out[obase + 1] = __fadd_rn(p.y, -cyc);
        out[obase + 2] = __fadd_rn(p.z, -czc);
    } else {
        out[obase + 0] = 0.0f;
        out[obase + 1] = 0.0f;
        out[obase + 2] = 0.0f;
    }

    // valid flag
    out[O_VALID + (unsigned)i] = valid ? 1.0f : 0.0f;
}

extern "C" void kernel_launch(void* const* d_in, const int* in_sizes, int n_in,
                              void* d_out, int out_size)
{
    const float4* pts = (const float4*)d_in[0];
    float* out = (float*)d_out;
    int threads = 256;
    int blocks = (BN_TOTAL + threads - 1) / threads;
    voxelizer_kernel<<<blocks, threads>>>(pts, out);
}